// round 15
// baseline (speedup 1.0000x reference)
#include <cuda_runtime.h>
#include <cuda_fp16.h>
#include <cstdint>

#define NB    8
#define NPOS  1024
#define CIN   256
#define HEADS 8
#define DH    64
#define AD    512
#define COUT  256
#define QK_SCALE 0.125f
#define GN_EPS 1e-5f
#define LOG2E 1.4426950408889634f

// ---------------------------------------------------------------------------
// helpers
// ---------------------------------------------------------------------------
__device__ __forceinline__ uint32_t smem_u32(const void* p) {
    uint32_t a;
    asm("{ .reg .u64 t; cvta.to.shared.u64 t, %1; cvt.u32.u64 %0, t; }" : "=r"(a) : "l"(p));
    return a;
}

__device__ __forceinline__ uint32_t pack_h2(float a, float b)
{
    __half2 h = __floats2half2_rn(a, b);
    return *reinterpret_cast<uint32_t*>(&h);
}

__device__ __forceinline__ void mma16816h(float* c, const uint32_t* a, const uint32_t* b)
{
    asm volatile("mma.sync.aligned.m16n8k16.row.col.f32.f16.f16.f32 "
        "{%0,%1,%2,%3},{%4,%5,%6,%7},{%8,%9},{%0,%1,%2,%3};"
        : "+f"(c[0]), "+f"(c[1]), "+f"(c[2]), "+f"(c[3])
        : "r"(a[0]), "r"(a[1]), "r"(a[2]), "r"(a[3]), "r"(b[0]), "r"(b[1]));
}

__device__ __forceinline__ void ldsm4(uint32_t* r, uint32_t addr)
{
    asm volatile("ldmatrix.sync.aligned.m8n8.x4.shared.b16 {%0,%1,%2,%3}, [%4];"
        : "=r"(r[0]), "=r"(r[1]), "=r"(r[2]), "=r"(r[3]) : "r"(addr));
}
__device__ __forceinline__ void ldsm4t(uint32_t* r, uint32_t addr)
{
    asm volatile("ldmatrix.sync.aligned.m8n8.x4.trans.shared.b16 {%0,%1,%2,%3}, [%4];"
        : "=r"(r[0]), "=r"(r[1]), "=r"(r[2]), "=r"(r[3]) : "r"(addr));
}

__device__ __forceinline__ void cp16(uint32_t dst, const void* src)
{
    asm volatile("cp.async.cg.shared.global [%0], [%1], 16;" :: "r"(dst), "l"(src));
}

__device__ __forceinline__ uint4 lds128(uint32_t addr)
{
    uint4 v;
    asm volatile("ld.shared.v4.u32 {%0,%1,%2,%3}, [%4];"
        : "=r"(v.x), "=r"(v.y), "=r"(v.z), "=r"(v.w) : "r"(addr));
    return v;
}

__device__ __forceinline__ uint32_t ex2_h2(uint32_t in)
{
    uint32_t r;
    asm volatile("ex2.approx.f16x2 %0, %1;" : "=r"(r) : "r"(in));
    return r;
}

// ---- smem tile helpers (out_mma path) ----
__device__ __forceinline__ uint32_t sw_addr(uint32_t base, int row, int ch) {
    return base + row * 128 + ((ch ^ (row & 7)) << 4);
}
__device__ __forceinline__ uint32_t afragT128_addr(uint32_t base, int k0, int m0, int lane) {
    int row = k0 + (lane & 7) + ((lane >> 4) & 1) * 8;
    int ch  = (m0 >> 3) + ((lane >> 3) & 1);
    return sw_addr(base, row, ch);
}
__device__ __forceinline__ uint32_t swp_off(int lrow, int ch) {
    int prow = lrow >> 1;
    int cp = ((lrow & 1) << 2) | ch;
    return (uint32_t)(prow * 128 + ((cp ^ (prow & 7)) << 4));
}
__device__ __forceinline__ uint32_t bfragP_addr(uint32_t base, int n0, int kc, int lane) {
    int lrow = n0 + (lane & 7) + ((lane >> 4) & 1) * 8;
    int ch   = 2 * kc + ((lane >> 3) & 1);
    return base + swp_off(lrow, ch);
}

// ---------------------------------------------------------------------------
// Scratch globals
// ---------------------------------------------------------------------------
__device__ uint4 g_Xf[512 * 16 * 32];
__device__ uint4 g_Wqf[96 * 16 * 32];
__device__ __half g_Wo[COUT * AD];
__device__ uint4 g_Qf[64 * 64 * 4 * 32];
__device__ uint4 g_Kf[64 * 64 * 4 * 32];
__device__ uint4 g_Vf[64 * 4 * 64 * 32];
__device__ __half g_A2[NB * AD * NPOS];
__device__ float g_Y[NB * NPOS * COUT];
__device__ float g_part[1024];

// ---------------------------------------------------------------------------
// Kernel 0a: X -> fp16 A-frag packed
// ---------------------------------------------------------------------------
__global__ __launch_bounds__(256) void conv_x_kernel(const float* __restrict__ X)
{
    int idx4 = blockIdx.x * 256 + threadIdx.x;
    int m  = idx4 >> 6;
    int c4 = (idx4 & 63) * 4;
    float4 v = reinterpret_cast<const float4*>(X)[idx4];

    uint32_t* Xf = reinterpret_cast<uint32_t*>(g_Xf);
    int mt = m >> 4;
    #pragma unroll
    for (int p = 0; p < 2; p++) {
        int c = c4 + p * 2;
        uint32_t pk = pack_h2(p ? v.z : v.x, p ? v.w : v.y);
        int kcg = c >> 4;
        int lane = (m & 7) * 4 + ((c & 7) >> 1);
        int reg  = ((m & 8) >> 3) | ((c & 8) >> 2);
        Xf[((size_t)(mt * 16 + kcg) * 32 + lane) * 4 + reg] = pk;
    }
}

// ---------------------------------------------------------------------------
// Kernel 0b: combined weight transpose + fp16
// ---------------------------------------------------------------------------
__global__ void conv_w2_kernel(const float* __restrict__ wq, const float* __restrict__ wo)
{
    const int which = blockIdx.z;
    if (which == 0 && blockIdx.y >= 8) return;
    if (which == 1 && blockIdx.x >= 8) return;
    const float* src = which ? wo : wq;
    const int K = which ? AD : CIN;
    const int N = which ? COUT : 3 * AD;

    __shared__ float tile[32][33];
    int n0 = blockIdx.x * 32;
    int k0 = blockIdx.y * 32;
    int tx = threadIdx.x, ty = threadIdx.y;
    tile[ty][tx] = src[(size_t)(k0 + ty) * N + n0 + tx];
    __syncthreads();
    if (tx < 16) {
        uint32_t pk = pack_h2(tile[2*tx][ty], tile[2*tx+1][ty]);
        int k = k0 + 2 * tx;
        int n = n0 + ty;
        if (which == 0) {
            uint32_t* Wf = reinterpret_cast<uint32_t*>(g_Wqf);
            int nt = n >> 4, kcg = k >> 4;
            int lane = (n & 7) * 4 + ((k & 7) >> 1);
            int reg  = ((k & 8) >> 3) | ((n & 8) >> 2);
            Wf[((size_t)(nt * 16 + kcg) * 32 + lane) * 4 + reg] = pk;
        } else {
            *reinterpret_cast<uint32_t*>(&g_Wo[(size_t)n * K + k]) = pk;
        }
    }
}

// ---------------------------------------------------------------------------
// Kernel 1: QKV GEMM — no smem, fp16 (unchanged).
// ---------------------------------------------------------------------------
__global__ __launch_bounds__(128) void qkv_mma_kernel()
{
    const int tid = threadIdx.x, lane = tid & 31, wid = tid >> 5;
    const int n_blk = blockIdx.x * 64;
    const int m_blk = blockIdx.y * 128;
    const int mw = (wid >> 1) * 64;
    const int nw = (wid & 1) * 32;
    const int g = lane >> 2;

    const int mt0 = (m_blk + mw) >> 4;
    const int nt0 = (n_blk + nw) >> 4;

    float acc[4][4][4];
    #pragma unroll
    for (int i = 0; i < 4; i++)
        #pragma unroll
        for (int j = 0; j < 4; j++)
            #pragma unroll
            for (int k = 0; k < 4; k++) acc[i][j][k] = 0.0f;

    uint4 af[2][4], bf[2][2];

    #pragma unroll
    for (int mf = 0; mf < 4; mf++)
        af[0][mf] = g_Xf[((size_t)(mt0 + mf) * 16 + 0) * 32 + lane];
    #pragma unroll
    for (int nf = 0; nf < 2; nf++)
        bf[0][nf] = g_Wqf[((size_t)(nt0 + nf) * 16 + 0) * 32 + lane];

    #pragma unroll
    for (int kcg = 0; kcg < 16; kcg++) {
        const int cur = kcg & 1;
        if (kcg < 15) {
            const int nxt = cur ^ 1;
            #pragma unroll
            for (int mf = 0; mf < 4; mf++)
                af[nxt][mf] = g_Xf[((size_t)(mt0 + mf) * 16 + (kcg + 1)) * 32 + lane];
            #pragma unroll
            for (int nf = 0; nf < 2; nf++)
                bf[nxt][nf] = g_Wqf[((size_t)(nt0 + nf) * 16 + (kcg + 1)) * 32 + lane];
        }
        #pragma unroll
        for (int mf = 0; mf < 4; mf++) {
            const uint32_t* a = reinterpret_cast<const uint32_t*>(&af[cur][mf]);
            #pragma unroll
            for (int nf = 0; nf < 2; nf++) {
                const uint32_t* b = reinterpret_cast<const uint32_t*>(&bf[cur][nf]);
                mma16816h(acc[mf][2*nf],   a, b + 0);
                mma16816h(acc[mf][2*nf+1], a, b + 2);
            }
        }
    }

    const int which = n_blk >> 9;
    const int h = (n_blk >> 6) & 7;

    if (which == 0) {
        #pragma unroll
        for (int mf = 0; mf < 4; mf++) {
            int r0 = m_blk + mw + mf*16 + g;
            int bh = (r0 >> 10) * HEADS + h;
            int mt = (r0 & 1023) >> 4;
            #pragma unroll
            for (int kco = 0; kco < 2; kco++) {
                int j0 = 2*kco, j1 = j0 + 1;
                uint32_t p0 = pack_h2(acc[mf][j0][0]*QK_SCALE, acc[mf][j0][1]*QK_SCALE);
                uint32_t p1 = pack_h2(acc[mf][j0][2]*QK_SCALE, acc[mf][j0][3]*QK_SCALE);
                uint32_t p2 = pack_h2(acc[mf][j1][0]*QK_SCALE, acc[mf][j1][1]*QK_SCALE);
                uint32_t p3 = pack_h2(acc[mf][j1][2]*QK_SCALE, acc[mf][j1][3]*QK_SCALE);
                int kcg = (nw >> 4) + kco;
                g_Qf[((size_t)(bh*64 + mt)*4 + kcg)*32 + lane] = make_uint4(p0, p1, p2, p3);
            }
        }
    } else if (which == 1) {
        #pragma unroll
        for (int mf = 0; mf < 4; mf++) {
            int r0 = m_blk + mw + mf*16 + g;
            int bh = (r0 >> 10) * HEADS + h;
            int nt = (r0 & 1023) >> 4;
            #pragma unroll
            for (int kco = 0; kco < 2; kco++) {
                int j0 = 2*kco, j1 = j0 + 1;
                uint32_t p0 = pack_h2(acc[mf][j0][0], acc[mf][j0][1]);
                uint32_t p1 = pack_h2(acc[mf][j1][0], acc[mf][j1][1]);
                uint32_t p2 = pack_h2(acc[mf][j0][2], acc[mf][j0][3]);
                uint32_t p3 = pack_h2(acc[mf][j1][2], acc[mf][j1][3]);
                int kcg = (nw >> 4) + kco;
                g_Kf[((size_t)(bh*64 + nt)*4 + kcg)*32 + lane] = make_uint4(p0, p1, p2, p3);
            }
        }
    } else {
        const int tigl = lane & 3;
        int odd = g & 1;
        #pragma unroll
        for (int mf = 0; mf < 4; mf++) {
            int r0 = m_blk + mw + mf*16 + g;
            int bh = (r0 >> 10) * HEADS + h;
            int kcgv = (r0 & 1023) >> 4;
            #pragma unroll
            for (int kco = 0; kco < 2; kco++) {
                int j0 = 2*kco, j1 = j0 + 1;
                float o00 = __shfl_xor_sync(0xffffffffu, acc[mf][j0][0], 4);
                float o01 = __shfl_xor_sync(0xffffffffu, acc[mf][j0][1], 4);
                float o02 = __shfl_xor_sync(0xffffffffu, acc[mf][j0][2], 4);
                float o03 = __shfl_xor_sync(0xffffffffu, acc[mf][j0][3], 4);
                float o10 = __shfl_xor_sync(0xffffffffu, acc[mf][j1][0], 4);
                float o11 = __shfl_xor_sync(0xffffffffu, acc[mf][j1][1], 4);
                float o12 = __shfl_xor_sync(0xffffffffu, acc[mf][j1][2], 4);
                float o13 = __shfl_xor_sync(0xffffffffu, acc[mf][j1][3], 4);
                float aE = odd ? o01 : acc[mf][j0][0];
                float aO = odd ? acc[mf][j0][1] : o00;
                float bE = odd ? o03 : acc[mf][j0][2];
                float bO = odd ? acc[mf][j0][3] : o02;
                float cE = odd ? o11 : acc[mf][j1][0];
                float cO = odd ? acc[mf][j1][1] : o10;
                float dE = odd ? o13 : acc[mf][j1][2];
                float dO = odd ? acc[mf][j1][3] : o12;
                uint32_t p0 = pack_h2(aE, aO);
                uint32_t p1 = pack_h2(bE, bO);
                uint32_t p2 = pack_h2(cE, cO);
                uint32_t p3 = pack_h2(dE, dO);
                int lane_t = tigl*8 + odd*4 + (g >> 1);
                int vt = (nw >> 4) + kco;
                g_Vf[((size_t)(bh*4 + vt)*64 + kcgv)*32 + lane_t] = make_uint4(p0, p1, p2, p3);
            }
        }
    }
}

// ---------------------------------------------------------------------------
// Kernel 2: attention — 32 q-rows/warp, per-key-group schedule (spill-free).
// Block = 128 q rows, grid (8, 64). Stage (16 KB): Kf[0,8K) Vf[8,16K).
// Per np (16 keys): compute S_np for both q tiles (4 K-frag loads), exp,
// immediately consume against V (4 V-frag loads) into O. K/V loads shared
// by both q tiles -> L1 bytes per q-row halved vs R14.
// ---------------------------------------------------------------------------
__global__ __launch_bounds__(128) void attn_mma_kernel()
{
    extern __shared__ uint8_t dyn_s[];
    const uint32_t sbase = smem_u32(dyn_s);

    const int tid  = threadIdx.x;
    const int lane = tid & 31;
    const int wid  = tid >> 5;
    const int bh   = blockIdx.y;
    const int qb   = blockIdx.x * 128 + wid * 32;
    const int g    = lane >> 2;
    const int tig  = lane & 3;

    uint4 qf[2][4];
    {
        int mt = qb >> 4;
        #pragma unroll
        for (int t = 0; t < 2; t++)
            #pragma unroll
            for (int kcg = 0; kcg < 4; kcg++)
                qf[t][kcg] = g_Qf[((size_t)(bh*64 + mt + t)*4 + kcg)*32 + lane];
    }

    float oc[2][8][4];
    #pragma unroll
    for (int t = 0; t < 2; t++)
        #pragma unroll
        for (int i = 0; i < 8; i++)
            #pragma unroll
            for (int j = 0; j < 4; j++) oc[t][i][j] = 0.0f;
    float ls[2][2] = {{0.0f, 0.0f}, {0.0f, 0.0f}};

    auto preload = [&](int kt, int buf) {
        uint32_t b0 = sbase + buf * 16384;
        const uint4* srcK = g_Kf + (size_t)(bh*64 + kt*4) * 128;
        #pragma unroll
        for (int i = 0; i < 4; i++) {
            int idx = i * 128 + tid;
            cp16(b0 + idx*16, srcK + idx);
        }
        #pragma unroll
        for (int vp = 0; vp < 4; vp++) {
            const uint4* srcV = g_Vf + ((size_t)(bh*4 + vp)*64 + kt*4) * 32;
            cp16(b0 + 8192 + vp*2048 + tid*16, srcV + tid);
        }
        asm volatile("cp.async.commit_group;" ::: "memory");
    };

    preload(0, 0);

    for (int kt = 0; kt < 16; kt++) {
        asm volatile("cp.async.wait_group 0;" ::: "memory");
        __syncthreads();
        if (kt < 15) preload(kt + 1, (kt + 1) & 1);

        const uint32_t b0 = sbase + (kt & 1) * 16384;
        const uint32_t sK = b0, sV = b0 + 8192;

        #pragma unroll
        for (int np = 0; np < 4; np++) {
            // ---- S_np = Q * K_np (both tiles share each K frag) ----
            float s[2][2][4];
            #pragma unroll
            for (int t = 0; t < 2; t++)
                #pragma unroll
                for (int i = 0; i < 2; i++)
                    #pragma unroll
                    for (int j = 0; j < 4; j++) s[t][i][j] = 0.0f;

            #pragma unroll
            for (int kcg = 0; kcg < 4; kcg++) {
                uint4 k4 = lds128(sK + (uint32_t)(((np*4 + kcg)*32 + lane) * 16));
                const uint32_t* b = reinterpret_cast<const uint32_t*>(&k4);
                #pragma unroll
                for (int t = 0; t < 2; t++) {
                    const uint32_t* q = reinterpret_cast<const uint32_t*>(&qf[t][kcg]);
                    mma16816h(s[t][0], q, b + 0);
                    mma16816h(s[t][1], q, b + 2);
                }
            }

            // ---- exp (f16x2 MUFU) + P frags ----
            uint32_t pp[2][4];
            #pragma unroll
            for (int t = 0; t < 2; t++) {
                pp[t][0] = ex2_h2(pack_h2(s[t][0][0]*LOG2E, s[t][0][1]*LOG2E));
                pp[t][1] = ex2_h2(pack_h2(s[t][0][2]*LOG2E, s[t][0][3]*LOG2E));
                pp[t][2] = ex2_h2(pack_h2(s[t][1][0]*LOG2E, s[t][1][1]*LOG2E));
                pp[t][3] = ex2_h2(pack_h2(s[t][1][2]*LOG2E, s[t][1][3]*LOG2E));
                float2 f0 = __half22float2(*reinterpret_cast<__half2*>(&pp[t][0]));
                float2 f1 = __half22float2(*reinterpret_cast<__half2*>(&pp[t][1]));
                float2 f2 = __half22float2(*reinterpret_cast<__half2*>(&pp[t][2]));
                float2 f3 = __half22float2(*reinterpret_cast<__half2*>(&pp[t][3]));
                ls[t][0] += f0.x + f0.y + f2.x + f2.y;
                ls[t][1] += f1.x + f1.y + f3.x + f3.y;
            }

            // ---- O += P_np * V_np (both tiles share each V frag) ----
            #pragma unroll
            for (int vp = 0; vp < 4; vp++) {
                uint4 v4 = lds128(sV + (uint32_t)(((vp*4 + np)*32 + lane) * 16));
                const uint32_t* b = reinterpret_cast<const uint32_t*>(&v4);
                #pragma unroll
                for (int t = 0; t < 2; t++) {
                    mma16816h(oc[t][2*vp],   pp[t], b + 0);
                    mma16816h(oc[t][2*vp+1], pp[t], b + 2);
                }
            }
        }
    }

    int b = bh >> 3, h = bh & 7;
    #pragma unroll
    for (int t = 0; t < 2; t++) {
        float l0 = ls[t][0], l1 = ls[t][1];
        l0 += __shfl_xor_sync(0xffffffffu, l0, 1);
        l0 += __shfl_xor_sync(0xffffffffu, l0, 2);
        l1 += __shfl_xor_sync(0xffffffffu, l1, 1);
        l1 += __shfl_xor_sync(0xffffffffu, l1, 2);
        float inv0 = 1.0f / l0;
        float inv1 = 1.0f / l1;

        int q0 = qb + t*16 + g, q1 = q0 + 8;
        size_t row0 = ((size_t)(b * AD + h * 64 + (q0 >> 4))) * NPOS + ((q0 & 15) << 6);
        size_t row1 = ((size_t)(b * AD + h * 64 + (q1 >> 4))) * NPOS + ((q1 & 15) << 6);
        #pragma unroll
        for (int ct = 0; ct < 8; ct++) {
            int c = ct * 8 + tig * 2;
            *reinterpret_cast<uint32_t*>(&g_A2[row0 + c]) =
                pack_h2(oc[t][ct][0] * inv0, oc[t][ct][1] * inv0);
            *reinterpret_cast<uint32_t*>(&g_A2[row1 + c]) =
                pack_h2(oc[t][ct][2] * inv1, oc[t][ct][3] * inv1);
        }
    }
}

// ---------------------------------------------------------------------------
// Kernel 3: out GEMM + fused GN partials (unchanged)
// ---------------------------------------------------------------------------
__global__ __launch_bounds__(128) void out_mma_kernel(const float* __restrict__ bout)
{
    extern __shared__ uint8_t dyn_o[];
    const uint32_t sbase = smem_u32(dyn_o);

    const int tid = threadIdx.x, lane = tid & 31, wid = tid >> 5;
    const int m_blk = blockIdx.x * 64;
    const int n_blk = blockIdx.y * 64;
    const int bb = blockIdx.z;
    const int mw = (wid >> 1) * 32;
    const int nw = (wid & 1) * 32;
    const int g = lane >> 2, tig = lane & 3;

    float acc[2][4][4];
    #pragma unroll
    for (int i = 0; i < 2; i++)
        #pragma unroll
        for (int j = 0; j < 4; j++)
            #pragma unroll
            for (int k = 0; k < 4; k++) acc[i][j][k] = 0.0f;

    const __half* A2 = g_A2 + (size_t)bb * AD * NPOS;

    auto preload = [&](int ks, int buf) {
        uint32_t b0 = sbase + buf * 8192;
        int k0 = ks * 32;
        #pragma unroll
        for (int i = 0; i < 2; i++) {
            int idx = i * 128 + tid;
            int row = idx >> 3, ch = idx & 7;
            uint32_t off = (uint32_t)(row * 128 + ((ch ^ (row & 7)) << 4));
            cp16(b0 + off, A2 + (size_t)(k0 + row) * NPOS + m_blk + ch * 8);
        }
        #pragma unroll
        for (int i = 0; i < 2; i++) {
            int idx = i * 128 + tid;
            int lrow = idx >> 2, ch = idx & 3;
            cp16(b0 + 4096 + swp_off(lrow, ch),
                 g_Wo + (size_t)(n_blk + lrow) * AD + k0 + ch * 8);
        }
        asm volatile("cp.async.commit_group;" ::: "memory");
    };

    preload(0, 0);

    for (int s = 0; s < 16; s++) {
        asm volatile("cp.async.wait_group 0;" ::: "memory");
        __syncthreads();
        if (s < 15) preload(s + 1, (s + 1) & 1);

        uint32_t b0 = sbase + (s & 1) * 8192;
        const uint32_t sA = b0, sB = b0 + 4096;

        #pragma unroll
        for (int kc = 0; kc < 2; kc++) {
            uint32_t b0f[4], b1f[4];
            ldsm4(b0f, bfragP_addr(sB, nw,      kc, lane));
            ldsm4(b1f, bfragP_addr(sB, nw + 16, kc, lane));
            #pragma unroll
            for (int mf = 0; mf < 2; mf++) {
                uint32_t a4[4];
                ldsm4t(a4, afragT128_addr(sA, kc*16, mw + mf*16, lane));
                mma16816h(acc[mf][0], a4, b0f + 0); mma16816h(acc[mf][1], a4, b0f + 2);
                mma16816h(acc[mf][2], a4, b1f + 0); mma16816h(acc[mf][3], a4, b1f + 2);
            }
        }
    }

    float psum = 0.0f, psq = 0.0f;
    #pragma unroll
    for (int mf = 0; mf < 2; mf++) {
        int r0 = m_blk + mw + mf*16 + g;
        #pragma unroll
        for (int j = 0; j < 4; j++) {
            int d = n_blk + nw + j * 8 + tig * 2;
            float2 bv = *reinterpret_cast<const float2*>(&bout[d]);
            float2 v0 = make_float2(acc[mf][j][0] + bv.x, acc[mf][j][1] + bv.y);
            float2 v1 = make_float2(acc[mf][j][2] + bv.x, acc[mf][j][3] + bv.y);
            *reinterpret_cast<float2*>(&g_Y[((size_t)bb*NPOS + r0)*COUT + d]) = v0;
            *reinterpret_cast<float2*>(&g_Y[((size_t)bb*NPOS + r0 + 8)*COUT + d]) = v1;
            psum += v0.x + v0.y + v1.x + v1.y;
            psq  += v0.x*v0.x + v0.y*v0.y + v1.x*v1.x + v1.y*v1.y;
        }
    }

    __syncthreads();
    float* rs  = reinterpret_cast<float*>(dyn_o);
    float* rss = rs + 128;
    rs[tid] = psum; rss[tid] = psq;
    __syncthreads();
    for (int st = 64; st > 0; st >>= 1) {
        if (tid < st) { rs[tid] += rs[tid + st]; rss[tid] += rss[tid + st]; }
        __syncthreads();
    }
    if (tid == 0) {
        int p = bb * 64 + blockIdx.x * 4 + blockIdx.y;
        g_part[2*p]   = rs[0];
        g_part[2*p+1] = rss[0];
    }
}

// ---------------------------------------------------------------------------
// Kernel 4: GN normalize with folded per-batch final reduction.
// ---------------------------------------------------------------------------
__global__ __launch_bounds__(256) void gn_norm_kernel(
    const float* __restrict__ gamma, const float* __restrict__ beta,
    float* __restrict__ out)
{
    __shared__ float ws[4];
    __shared__ float sm_mean, sm_rstd;

    int idx4 = blockIdx.x * 256 + threadIdx.x;
    int b  = idx4 >> 16;
    int tid = threadIdx.x;

    if (tid < 64) {
        float s  = g_part[2*(b*64 + tid)];
        float ss = g_part[2*(b*64 + tid) + 1];
        #pragma unroll
        for (int o = 16; o > 0; o >>= 1) {
            s  += __shfl_down_sync(0xffffffffu, s, o);
            ss += __shfl_down_sync(0xffffffffu, ss, o);
        }
        if ((tid & 31) == 0) {
            ws[(tid >> 5) * 2]     = s;
            ws[(tid >> 5) * 2 + 1] = ss;
        }
    }
    __syncthreads();
    if (tid == 0) {
        const float inv_n = 1.0f / (float)(NPOS * COUT);
        float S  = ws[0] + ws[2];
        float SS = ws[1] + ws[3];
        float mean = S * inv_n;
        float var  = SS * inv_n - mean * mean;
        sm_mean = mean;
        sm_rstd = rsqrtf(var + GN_EPS);
    }
    __syncthreads();

    float mean = sm_mean;
    float rstd = sm_rstd;
    int d4 = idx4 & 63;

    float4 y  = reinterpret_cast<const float4*>(g_Y)[idx4];
    float4 g  = reinterpret_cast<const float4*>(gamma)[d4];
    float4 be = reinterpret_cast<const float4*>(beta)[d4];

    float4 r;
    r.x = (y.x - mean) * rstd * g.x + be.x;
    r.y = (y.y - mean) * rstd * g.y + be.y;
    r.z = (y.z - mean) * rstd * g.z + be.z;
    r.w = (y.w - mean) * rstd * g.w + be.w;
    reinterpret_cast<float4*>(out)[idx4] = r;
}

// ---------------------------------------------------------------------------
extern "C" void kernel_launch(void* const* d_in, const int* in_sizes, int n_in,
                              void* d_out, int out_size)
{
    const float* x      = (const float*)d_in[0];
    const float* w_qkv  = (const float*)d_in[1];
    const float* w_out  = (const float*)d_in[2];
    const float* b_out  = (const float*)d_in[3];
    const float* gamma  = (const float*)d_in[4];
    const float* beta   = (const float*)d_in[5];
    float* out = (float*)d_out;

    static int smem_set = 0;
    if (!smem_set) {
        cudaFuncSetAttribute(attn_mma_kernel,
                             cudaFuncAttributeMaxDynamicSharedMemorySize, 32768);
        cudaFuncSetAttribute(out_mma_kernel,
                             cudaFuncAttributeMaxDynamicSharedMemorySize, 16384);
        smem_set = 1;
    }

    conv_x_kernel<<<2048, 256>>>(x);
    conv_w2_kernel<<<dim3(48, 16, 2), dim3(32, 32)>>>(w_qkv, w_out);
    qkv_mma_kernel<<<dim3(24, 64), 128>>>();
    attn_mma_kernel<<<dim3(8, 64), 128, 32768>>>();
    out_mma_kernel<<<dim3(16, 4, 8), 128, 16384>>>(b_out);
    gn_norm_kernel<<<2048, 256>>>(gamma, beta, out);
}

// round 16
// speedup vs baseline: 1.0789x; 1.0789x over previous
#include <cuda_runtime.h>
#include <cuda_fp16.h>
#include <cstdint>

#define NB    8
#define NPOS  1024
#define CIN   256
#define HEADS 8
#define DH    64
#define AD    512
#define COUT  256
#define QK_SCALE 0.125f
#define GN_EPS 1e-5f
#define LOG2E 1.4426950408889634f

// ---------------------------------------------------------------------------
// helpers
// ---------------------------------------------------------------------------
__device__ __forceinline__ uint32_t smem_u32(const void* p) {
    uint32_t a;
    asm("{ .reg .u64 t; cvta.to.shared.u64 t, %1; cvt.u32.u64 %0, t; }" : "=r"(a) : "l"(p));
    return a;
}

__device__ __forceinline__ uint32_t pack_h2(float a, float b)
{
    __half2 h = __floats2half2_rn(a, b);
    return *reinterpret_cast<uint32_t*>(&h);
}

__device__ __forceinline__ void mma16816h(float* c, const uint32_t* a, const uint32_t* b)
{
    asm volatile("mma.sync.aligned.m16n8k16.row.col.f32.f16.f16.f32 "
        "{%0,%1,%2,%3},{%4,%5,%6,%7},{%8,%9},{%0,%1,%2,%3};"
        : "+f"(c[0]), "+f"(c[1]), "+f"(c[2]), "+f"(c[3])
        : "r"(a[0]), "r"(a[1]), "r"(a[2]), "r"(a[3]), "r"(b[0]), "r"(b[1]));
}

__device__ __forceinline__ void ldsm4(uint32_t* r, uint32_t addr)
{
    asm volatile("ldmatrix.sync.aligned.m8n8.x4.shared.b16 {%0,%1,%2,%3}, [%4];"
        : "=r"(r[0]), "=r"(r[1]), "=r"(r[2]), "=r"(r[3]) : "r"(addr));
}
__device__ __forceinline__ void ldsm4t(uint32_t* r, uint32_t addr)
{
    asm volatile("ldmatrix.sync.aligned.m8n8.x4.trans.shared.b16 {%0,%1,%2,%3}, [%4];"
        : "=r"(r[0]), "=r"(r[1]), "=r"(r[2]), "=r"(r[3]) : "r"(addr));
}

__device__ __forceinline__ void cp16(uint32_t dst, const void* src)
{
    asm volatile("cp.async.cg.shared.global [%0], [%1], 16;" :: "r"(dst), "l"(src));
}

__device__ __forceinline__ uint4 lds128(uint32_t addr)
{
    uint4 v;
    asm volatile("ld.shared.v4.u32 {%0,%1,%2,%3}, [%4];"
        : "=r"(v.x), "=r"(v.y), "=r"(v.z), "=r"(v.w) : "r"(addr));
    return v;
}

__device__ __forceinline__ uint32_t ex2_h2(uint32_t in)
{
    uint32_t r;
    asm volatile("ex2.approx.f16x2 %0, %1;" : "=r"(r) : "r"(in));
    return r;
}

// ---- smem tile helpers (out_mma path) ----
__device__ __forceinline__ uint32_t sw_addr(uint32_t base, int row, int ch) {
    return base + row * 128 + ((ch ^ (row & 7)) << 4);
}
__device__ __forceinline__ uint32_t afragT128_addr(uint32_t base, int k0, int m0, int lane) {
    int row = k0 + (lane & 7) + ((lane >> 4) & 1) * 8;
    int ch  = (m0 >> 3) + ((lane >> 3) & 1);
    return sw_addr(base, row, ch);
}
__device__ __forceinline__ uint32_t swp_off(int lrow, int ch) {
    int prow = lrow >> 1;
    int cp = ((lrow & 1) << 2) | ch;
    return (uint32_t)(prow * 128 + ((cp ^ (prow & 7)) << 4));
}
__device__ __forceinline__ uint32_t bfragP_addr(uint32_t base, int n0, int kc, int lane) {
    int lrow = n0 + (lane & 7) + ((lane >> 4) & 1) * 8;
    int ch   = 2 * kc + ((lane >> 3) & 1);
    return base + swp_off(lrow, ch);
}

// ---------------------------------------------------------------------------
// Scratch globals
// ---------------------------------------------------------------------------
__device__ uint4 g_Xf[512 * 16 * 32];
__device__ uint4 g_Wqf[96 * 16 * 32];
__device__ __half g_Wo[COUT * AD];
__device__ uint4 g_Qf[64 * 64 * 4 * 32];
__device__ uint4 g_Kf[64 * 64 * 4 * 32];
__device__ uint4 g_Vf[64 * 4 * 64 * 32];
__device__ __half g_A2[NB * AD * NPOS];
__device__ float g_Y[NB * NPOS * COUT];
__device__ float g_part[1024];

// ---------------------------------------------------------------------------
// Kernel 0a: X -> fp16 A-frag packed
// ---------------------------------------------------------------------------
__global__ __launch_bounds__(256) void conv_x_kernel(const float* __restrict__ X)
{
    int idx4 = blockIdx.x * 256 + threadIdx.x;
    int m  = idx4 >> 6;
    int c4 = (idx4 & 63) * 4;
    float4 v = reinterpret_cast<const float4*>(X)[idx4];

    uint32_t* Xf = reinterpret_cast<uint32_t*>(g_Xf);
    int mt = m >> 4;
    #pragma unroll
    for (int p = 0; p < 2; p++) {
        int c = c4 + p * 2;
        uint32_t pk = pack_h2(p ? v.z : v.x, p ? v.w : v.y);
        int kcg = c >> 4;
        int lane = (m & 7) * 4 + ((c & 7) >> 1);
        int reg  = ((m & 8) >> 3) | ((c & 8) >> 2);
        Xf[((size_t)(mt * 16 + kcg) * 32 + lane) * 4 + reg] = pk;
    }
}

// ---------------------------------------------------------------------------
// Kernel 0b: combined weight transpose + fp16
// ---------------------------------------------------------------------------
__global__ void conv_w2_kernel(const float* __restrict__ wq, const float* __restrict__ wo)
{
    const int which = blockIdx.z;
    if (which == 0 && blockIdx.y >= 8) return;
    if (which == 1 && blockIdx.x >= 8) return;
    const float* src = which ? wo : wq;
    const int K = which ? AD : CIN;
    const int N = which ? COUT : 3 * AD;

    __shared__ float tile[32][33];
    int n0 = blockIdx.x * 32;
    int k0 = blockIdx.y * 32;
    int tx = threadIdx.x, ty = threadIdx.y;
    tile[ty][tx] = src[(size_t)(k0 + ty) * N + n0 + tx];
    __syncthreads();
    if (tx < 16) {
        uint32_t pk = pack_h2(tile[2*tx][ty], tile[2*tx+1][ty]);
        int k = k0 + 2 * tx;
        int n = n0 + ty;
        if (which == 0) {
            uint32_t* Wf = reinterpret_cast<uint32_t*>(g_Wqf);
            int nt = n >> 4, kcg = k >> 4;
            int lane = (n & 7) * 4 + ((k & 7) >> 1);
            int reg  = ((k & 8) >> 3) | ((n & 8) >> 2);
            Wf[((size_t)(nt * 16 + kcg) * 32 + lane) * 4 + reg] = pk;
        } else {
            *reinterpret_cast<uint32_t*>(&g_Wo[(size_t)n * K + k]) = pk;
        }
    }
}

// ---------------------------------------------------------------------------
// Kernel 1: QKV GEMM — no smem, fp16 (unchanged).
// ---------------------------------------------------------------------------
__global__ __launch_bounds__(128) void qkv_mma_kernel()
{
    const int tid = threadIdx.x, lane = tid & 31, wid = tid >> 5;
    const int n_blk = blockIdx.x * 64;
    const int m_blk = blockIdx.y * 128;
    const int mw = (wid >> 1) * 64;
    const int nw = (wid & 1) * 32;
    const int g = lane >> 2;

    const int mt0 = (m_blk + mw) >> 4;
    const int nt0 = (n_blk + nw) >> 4;

    float acc[4][4][4];
    #pragma unroll
    for (int i = 0; i < 4; i++)
        #pragma unroll
        for (int j = 0; j < 4; j++)
            #pragma unroll
            for (int k = 0; k < 4; k++) acc[i][j][k] = 0.0f;

    uint4 af[2][4], bf[2][2];

    #pragma unroll
    for (int mf = 0; mf < 4; mf++)
        af[0][mf] = g_Xf[((size_t)(mt0 + mf) * 16 + 0) * 32 + lane];
    #pragma unroll
    for (int nf = 0; nf < 2; nf++)
        bf[0][nf] = g_Wqf[((size_t)(nt0 + nf) * 16 + 0) * 32 + lane];

    #pragma unroll
    for (int kcg = 0; kcg < 16; kcg++) {
        const int cur = kcg & 1;
        if (kcg < 15) {
            const int nxt = cur ^ 1;
            #pragma unroll
            for (int mf = 0; mf < 4; mf++)
                af[nxt][mf] = g_Xf[((size_t)(mt0 + mf) * 16 + (kcg + 1)) * 32 + lane];
            #pragma unroll
            for (int nf = 0; nf < 2; nf++)
                bf[nxt][nf] = g_Wqf[((size_t)(nt0 + nf) * 16 + (kcg + 1)) * 32 + lane];
        }
        #pragma unroll
        for (int mf = 0; mf < 4; mf++) {
            const uint32_t* a = reinterpret_cast<const uint32_t*>(&af[cur][mf]);
            #pragma unroll
            for (int nf = 0; nf < 2; nf++) {
                const uint32_t* b = reinterpret_cast<const uint32_t*>(&bf[cur][nf]);
                mma16816h(acc[mf][2*nf],   a, b + 0);
                mma16816h(acc[mf][2*nf+1], a, b + 2);
            }
        }
    }

    const int which = n_blk >> 9;
    const int h = (n_blk >> 6) & 7;

    if (which == 0) {
        #pragma unroll
        for (int mf = 0; mf < 4; mf++) {
            int r0 = m_blk + mw + mf*16 + g;
            int bh = (r0 >> 10) * HEADS + h;
            int mt = (r0 & 1023) >> 4;
            #pragma unroll
            for (int kco = 0; kco < 2; kco++) {
                int j0 = 2*kco, j1 = j0 + 1;
                uint32_t p0 = pack_h2(acc[mf][j0][0]*QK_SCALE, acc[mf][j0][1]*QK_SCALE);
                uint32_t p1 = pack_h2(acc[mf][j0][2]*QK_SCALE, acc[mf][j0][3]*QK_SCALE);
                uint32_t p2 = pack_h2(acc[mf][j1][0]*QK_SCALE, acc[mf][j1][1]*QK_SCALE);
                uint32_t p3 = pack_h2(acc[mf][j1][2]*QK_SCALE, acc[mf][j1][3]*QK_SCALE);
                int kcg = (nw >> 4) + kco;
                g_Qf[((size_t)(bh*64 + mt)*4 + kcg)*32 + lane] = make_uint4(p0, p1, p2, p3);
            }
        }
    } else if (which == 1) {
        #pragma unroll
        for (int mf = 0; mf < 4; mf++) {
            int r0 = m_blk + mw + mf*16 + g;
            int bh = (r0 >> 10) * HEADS + h;
            int nt = (r0 & 1023) >> 4;
            #pragma unroll
            for (int kco = 0; kco < 2; kco++) {
                int j0 = 2*kco, j1 = j0 + 1;
                uint32_t p0 = pack_h2(acc[mf][j0][0], acc[mf][j0][1]);
                uint32_t p1 = pack_h2(acc[mf][j1][0], acc[mf][j1][1]);
                uint32_t p2 = pack_h2(acc[mf][j0][2], acc[mf][j0][3]);
                uint32_t p3 = pack_h2(acc[mf][j1][2], acc[mf][j1][3]);
                int kcg = (nw >> 4) + kco;
                g_Kf[((size_t)(bh*64 + nt)*4 + kcg)*32 + lane] = make_uint4(p0, p1, p2, p3);
            }
        }
    } else {
        const int tigl = lane & 3;
        int odd = g & 1;
        #pragma unroll
        for (int mf = 0; mf < 4; mf++) {
            int r0 = m_blk + mw + mf*16 + g;
            int bh = (r0 >> 10) * HEADS + h;
            int kcgv = (r0 & 1023) >> 4;
            #pragma unroll
            for (int kco = 0; kco < 2; kco++) {
                int j0 = 2*kco, j1 = j0 + 1;
                float o00 = __shfl_xor_sync(0xffffffffu, acc[mf][j0][0], 4);
                float o01 = __shfl_xor_sync(0xffffffffu, acc[mf][j0][1], 4);
                float o02 = __shfl_xor_sync(0xffffffffu, acc[mf][j0][2], 4);
                float o03 = __shfl_xor_sync(0xffffffffu, acc[mf][j0][3], 4);
                float o10 = __shfl_xor_sync(0xffffffffu, acc[mf][j1][0], 4);
                float o11 = __shfl_xor_sync(0xffffffffu, acc[mf][j1][1], 4);
                float o12 = __shfl_xor_sync(0xffffffffu, acc[mf][j1][2], 4);
                float o13 = __shfl_xor_sync(0xffffffffu, acc[mf][j1][3], 4);
                float aE = odd ? o01 : acc[mf][j0][0];
                float aO = odd ? acc[mf][j0][1] : o00;
                float bE = odd ? o03 : acc[mf][j0][2];
                float bO = odd ? acc[mf][j0][3] : o02;
                float cE = odd ? o11 : acc[mf][j1][0];
                float cO = odd ? acc[mf][j1][1] : o10;
                float dE = odd ? o13 : acc[mf][j1][2];
                float dO = odd ? acc[mf][j1][3] : o12;
                uint32_t p0 = pack_h2(aE, aO);
                uint32_t p1 = pack_h2(bE, bO);
                uint32_t p2 = pack_h2(cE, cO);
                uint32_t p3 = pack_h2(dE, dO);
                int lane_t = tigl*8 + odd*4 + (g >> 1);
                int vt = (nw >> 4) + kco;
                g_Vf[((size_t)(bh*4 + vt)*64 + kcgv)*32 + lane_t] = make_uint4(p0, p1, p2, p3);
            }
        }
    }
}

// ---------------------------------------------------------------------------
// Kernel 2: attention — R14 shape (16 q-rows/warp, grid (16,64)), f16x2 exp,
// softmax denominator via ones-MMA (lacc += P * 1): no cvt/fadd bookkeeping,
// no final shuffle reduction.
// ---------------------------------------------------------------------------
__global__ __launch_bounds__(128) void attn_mma_kernel()
{
    extern __shared__ uint8_t dyn_s[];
    const uint32_t sbase = smem_u32(dyn_s);

    const int tid  = threadIdx.x;
    const int lane = tid & 31;
    const int wid  = tid >> 5;
    const int bh   = blockIdx.y;
    const int qb   = blockIdx.x * 64 + wid * 16;
    const int g    = lane >> 2;
    const int tig  = lane & 3;

    uint4 qf[4];
    {
        int mt = qb >> 4;
        #pragma unroll
        for (int kcg = 0; kcg < 4; kcg++)
            qf[kcg] = g_Qf[((size_t)(bh*64 + mt)*4 + kcg)*32 + lane];
    }

    float oc[8][4];
    #pragma unroll
    for (int i = 0; i < 8; i++)
        #pragma unroll
        for (int j = 0; j < 4; j++) oc[i][j] = 0.0f;
    float lacc[4] = {0.0f, 0.0f, 0.0f, 0.0f};
    const uint32_t ones2[2] = {0x3C003C00u, 0x3C003C00u};

    auto preload = [&](int kt, int buf) {
        uint32_t b0 = sbase + buf * 16384;
        const uint4* srcK = g_Kf + (size_t)(bh*64 + kt*4) * 128;
        #pragma unroll
        for (int i = 0; i < 4; i++) {
            int idx = i * 128 + tid;
            cp16(b0 + idx*16, srcK + idx);
        }
        #pragma unroll
        for (int vp = 0; vp < 4; vp++) {
            const uint4* srcV = g_Vf + ((size_t)(bh*4 + vp)*64 + kt*4) * 32;
            cp16(b0 + 8192 + vp*2048 + tid*16, srcV + tid);
        }
        asm volatile("cp.async.commit_group;" ::: "memory");
    };

    preload(0, 0);

    for (int kt = 0; kt < 16; kt++) {
        asm volatile("cp.async.wait_group 0;" ::: "memory");
        __syncthreads();
        if (kt < 15) preload(kt + 1, (kt + 1) & 1);

        const uint32_t b0 = sbase + (kt & 1) * 16384;
        const uint32_t sK = b0, sV = b0 + 8192;

        float s[8][4];
        #pragma unroll
        for (int i = 0; i < 8; i++)
            #pragma unroll
            for (int j = 0; j < 4; j++) s[i][j] = 0.0f;

        #pragma unroll
        for (int kcg = 0; kcg < 4; kcg++) {
            const uint32_t* q = reinterpret_cast<const uint32_t*>(&qf[kcg]);
            #pragma unroll
            for (int np = 0; np < 4; np++) {
                uint4 k4 = lds128(sK + (uint32_t)(((np*4 + kcg)*32 + lane) * 16));
                const uint32_t* b = reinterpret_cast<const uint32_t*>(&k4);
                mma16816h(s[2*np],   q, b + 0);
                mma16816h(s[2*np+1], q, b + 2);
            }
        }

        // ---- exp (f16x2 MUFU); denominator via ones-MMA ----
        uint32_t pp[4][4];
        #pragma unroll
        for (int np = 0; np < 4; np++) {
            pp[np][0] = ex2_h2(pack_h2(s[2*np][0]*LOG2E,   s[2*np][1]*LOG2E));
            pp[np][1] = ex2_h2(pack_h2(s[2*np][2]*LOG2E,   s[2*np][3]*LOG2E));
            pp[np][2] = ex2_h2(pack_h2(s[2*np+1][0]*LOG2E, s[2*np+1][1]*LOG2E));
            pp[np][3] = ex2_h2(pack_h2(s[2*np+1][2]*LOG2E, s[2*np+1][3]*LOG2E));
            mma16816h(lacc, pp[np], ones2);
        }

        // ---- O += P*V ----
        #pragma unroll
        for (int jc = 0; jc < 4; jc++) {
            #pragma unroll
            for (int vp = 0; vp < 4; vp++) {
                uint4 v4 = lds128(sV + (uint32_t)(((vp*4 + jc)*32 + lane) * 16));
                const uint32_t* b = reinterpret_cast<const uint32_t*>(&v4);
                mma16816h(oc[2*vp],   pp[jc], b + 0);
                mma16816h(oc[2*vp+1], pp[jc], b + 2);
            }
        }
    }

    // lacc[0] = full denominator for row g; lacc[2] for row g+8 (exact, fp32,
    // identical across the quad — no shuffle needed).
    float inv0 = 1.0f / lacc[0];
    float inv1 = 1.0f / lacc[2];

    int b = bh >> 3, h = bh & 7;
    int q0 = qb + g, q1 = qb + g + 8;
    size_t row0 = ((size_t)(b * AD + h * 64 + (q0 >> 4))) * NPOS + ((q0 & 15) << 6);
    size_t row1 = ((size_t)(b * AD + h * 64 + (q1 >> 4))) * NPOS + ((q1 & 15) << 6);
    #pragma unroll
    for (int ct = 0; ct < 8; ct++) {
        int c = ct * 8 + tig * 2;
        *reinterpret_cast<uint32_t*>(&g_A2[row0 + c]) =
            pack_h2(oc[ct][0] * inv0, oc[ct][1] * inv0);
        *reinterpret_cast<uint32_t*>(&g_A2[row1 + c]) =
            pack_h2(oc[ct][2] * inv1, oc[ct][3] * inv1);
    }
}

// ---------------------------------------------------------------------------
// Kernel 3: out GEMM + fused GN partials (unchanged)
// ---------------------------------------------------------------------------
__global__ __launch_bounds__(128) void out_mma_kernel(const float* __restrict__ bout)
{
    extern __shared__ uint8_t dyn_o[];
    const uint32_t sbase = smem_u32(dyn_o);

    const int tid = threadIdx.x, lane = tid & 31, wid = tid >> 5;
    const int m_blk = blockIdx.x * 64;
    const int n_blk = blockIdx.y * 64;
    const int bb = blockIdx.z;
    const int mw = (wid >> 1) * 32;
    const int nw = (wid & 1) * 32;
    const int g = lane >> 2, tig = lane & 3;

    float acc[2][4][4];
    #pragma unroll
    for (int i = 0; i < 2; i++)
        #pragma unroll
        for (int j = 0; j < 4; j++)
            #pragma unroll
            for (int k = 0; k < 4; k++) acc[i][j][k] = 0.0f;

    const __half* A2 = g_A2 + (size_t)bb * AD * NPOS;

    auto preload = [&](int ks, int buf) {
        uint32_t b0 = sbase + buf * 8192;
        int k0 = ks * 32;
        #pragma unroll
        for (int i = 0; i < 2; i++) {
            int idx = i * 128 + tid;
            int row = idx >> 3, ch = idx & 7;
            uint32_t off = (uint32_t)(row * 128 + ((ch ^ (row & 7)) << 4));
            cp16(b0 + off, A2 + (size_t)(k0 + row) * NPOS + m_blk + ch * 8);
        }
        #pragma unroll
        for (int i = 0; i < 2; i++) {
            int idx = i * 128 + tid;
            int lrow = idx >> 2, ch = idx & 3;
            cp16(b0 + 4096 + swp_off(lrow, ch),
                 g_Wo + (size_t)(n_blk + lrow) * AD + k0 + ch * 8);
        }
        asm volatile("cp.async.commit_group;" ::: "memory");
    };

    preload(0, 0);

    for (int s = 0; s < 16; s++) {
        asm volatile("cp.async.wait_group 0;" ::: "memory");
        __syncthreads();
        if (s < 15) preload(s + 1, (s + 1) & 1);

        uint32_t b0 = sbase + (s & 1) * 8192;
        const uint32_t sA = b0, sB = b0 + 4096;

        #pragma unroll
        for (int kc = 0; kc < 2; kc++) {
            uint32_t b0f[4], b1f[4];
            ldsm4(b0f, bfragP_addr(sB, nw,      kc, lane));
            ldsm4(b1f, bfragP_addr(sB, nw + 16, kc, lane));
            #pragma unroll
            for (int mf = 0; mf < 2; mf++) {
                uint32_t a4[4];
                ldsm4t(a4, afragT128_addr(sA, kc*16, mw + mf*16, lane));
                mma16816h(acc[mf][0], a4, b0f + 0); mma16816h(acc[mf][1], a4, b0f + 2);
                mma16816h(acc[mf][2], a4, b1f + 0); mma16816h(acc[mf][3], a4, b1f + 2);
            }
        }
    }

    float psum = 0.0f, psq = 0.0f;
    #pragma unroll
    for (int mf = 0; mf < 2; mf++) {
        int r0 = m_blk + mw + mf*16 + g;
        #pragma unroll
        for (int j = 0; j < 4; j++) {
            int d = n_blk + nw + j * 8 + tig * 2;
            float2 bv = *reinterpret_cast<const float2*>(&bout[d]);
            float2 v0 = make_float2(acc[mf][j][0] + bv.x, acc[mf][j][1] + bv.y);
            float2 v1 = make_float2(acc[mf][j][2] + bv.x, acc[mf][j][3] + bv.y);
            *reinterpret_cast<float2*>(&g_Y[((size_t)bb*NPOS + r0)*COUT + d]) = v0;
            *reinterpret_cast<float2*>(&g_Y[((size_t)bb*NPOS + r0 + 8)*COUT + d]) = v1;
            psum += v0.x + v0.y + v1.x + v1.y;
            psq  += v0.x*v0.x + v0.y*v0.y + v1.x*v1.x + v1.y*v1.y;
        }
    }

    __syncthreads();
    float* rs  = reinterpret_cast<float*>(dyn_o);
    float* rss = rs + 128;
    rs[tid] = psum; rss[tid] = psq;
    __syncthreads();
    for (int st = 64; st > 0; st >>= 1) {
        if (tid < st) { rs[tid] += rs[tid + st]; rss[tid] += rss[tid + st]; }
        __syncthreads();
    }
    if (tid == 0) {
        int p = bb * 64 + blockIdx.x * 4 + blockIdx.y;
        g_part[2*p]   = rs[0];
        g_part[2*p+1] = rss[0];
    }
}

// ---------------------------------------------------------------------------
// Kernel 4: GN normalize with folded per-batch final reduction.
// ---------------------------------------------------------------------------
__global__ __launch_bounds__(256) void gn_norm_kernel(
    const float* __restrict__ gamma, const float* __restrict__ beta,
    float* __restrict__ out)
{
    __shared__ float ws[4];
    __shared__ float sm_mean, sm_rstd;

    int idx4 = blockIdx.x * 256 + threadIdx.x;
    int b  = idx4 >> 16;
    int tid = threadIdx.x;

    if (tid < 64) {
        float s  = g_part[2*(b*64 + tid)];
        float ss = g_part[2*(b*64 + tid) + 1];
        #pragma unroll
        for (int o = 16; o > 0; o >>= 1) {
            s  += __shfl_down_sync(0xffffffffu, s, o);
            ss += __shfl_down_sync(0xffffffffu, ss, o);
        }
        if ((tid & 31) == 0) {
            ws[(tid >> 5) * 2]     = s;
            ws[(tid >> 5) * 2 + 1] = ss;
        }
    }
    __syncthreads();
    if (tid == 0) {
        const float inv_n = 1.0f / (float)(NPOS * COUT);
        float S  = ws[0] + ws[2];
        float SS = ws[1] + ws[3];
        float mean = S * inv_n;
        float var  = SS * inv_n - mean * mean;
        sm_mean = mean;
        sm_rstd = rsqrtf(var + GN_EPS);
    }
    __syncthreads();

    float mean = sm_mean;
    float rstd = sm_rstd;
    int d4 = idx4 & 63;

    float4 y  = reinterpret_cast<const float4*>(g_Y)[idx4];
    float4 g  = reinterpret_cast<const float4*>(gamma)[d4];
    float4 be = reinterpret_cast<const float4*>(beta)[d4];

    float4 r;
    r.x = (y.x - mean) * rstd * g.x + be.x;
    r.y = (y.y - mean) * rstd * g.y + be.y;
    r.z = (y.z - mean) * rstd * g.z + be.z;
    r.w = (y.w - mean) * rstd * g.w + be.w;
    reinterpret_cast<float4*>(out)[idx4] = r;
}

// ---------------------------------------------------------------------------
extern "C" void kernel_launch(void* const* d_in, const int* in_sizes, int n_in,
                              void* d_out, int out_size)
{
    const float* x      = (const float*)d_in[0];
    const float* w_qkv  = (const float*)d_in[1];
    const float* w_out  = (const float*)d_in[2];
    const float* b_out  = (const float*)d_in[3];
    const float* gamma  = (const float*)d_in[4];
    const float* beta   = (const float*)d_in[5];
    float* out = (float*)d_out;

    static int smem_set = 0;
    if (!smem_set) {
        cudaFuncSetAttribute(attn_mma_kernel,
                             cudaFuncAttributeMaxDynamicSharedMemorySize, 32768);
        cudaFuncSetAttribute(out_mma_kernel,
                             cudaFuncAttributeMaxDynamicSharedMemorySize, 16384);
        smem_set = 1;
    }

    conv_x_kernel<<<2048, 256>>>(x);
    conv_w2_kernel<<<dim3(48, 16, 2), dim3(32, 32)>>>(w_qkv, w_out);
    qkv_mma_kernel<<<dim3(24, 64), 128>>>();
    attn_mma_kernel<<<dim3(16, 64), 128, 32768>>>();
    out_mma_kernel<<<dim3(16, 4, 8), 128, 16384>>>(b_out);
    gn_norm_kernel<<<2048, 256>>>(gamma, beta, out);
}